// round 1
// baseline (speedup 1.0000x reference)
#include <cuda_runtime.h>

// MacUnit: out[b, 2*ic+k] = attention[2*ic+k] * f3(data[b, ic])
// where f3 = 3 iterations of x += step(x)/3, step = interpolated trig activation.
//
// B=32768, IN_CH=512, OUT_CH=1024, NUM_POINTS=17, NUM_STEPS=3.
// The IN_CH_FACTOR=2 broadcast dim is redundant (elementwise steps keep the
// two copies identical), so we compute once per input element and fan out x2.

#define NUM_POINTS 17
#define IN_CH 512
#define OUT_CH 1024

__global__ __launch_bounds__(256, 8)
void macunit_kernel(const float4* __restrict__ data,
                    const float* __restrict__ angles,
                    const float* __restrict__ velocity,
                    const float4* __restrict__ att,     // 1024 floats = 256 float4
                    const float* __restrict__ coeff,
                    const float* __restrict__ bias,
                    float4* __restrict__ out)           // [B, 256] float4
{
    __shared__ float s_ang[NUM_POINTS];
    __shared__ float s_vel[NUM_POINTS];
    const int t = threadIdx.x;
    if (t < NUM_POINTS) {
        s_ang[t] = angles[t];
        s_vel[t] = velocity[t];
    }
    __syncthreads();

    const float c  = __ldg(coeff);
    const float bs = __ldg(bias);
    // tanh(z) = 1 - 2/(exp(2z)+1); fold the 2x into the fma.
    const float c2 = 2.0f * c;
    const float b2 = 2.0f * bs;

    const int g = blockIdx.x * 256 + t;          // 0 .. B*IN_CH/4 - 1  (4,194,304)
    const float4 d = data[g];

    float y0 = d.x, y1 = d.y, y2 = d.z, y3 = d.w;

    #pragma unroll
    for (int s = 0; s < 3; s++) {
        #pragma unroll
        for (int j = 0; j < 4; j++) {
            float x = (j == 0) ? y0 : (j == 1) ? y1 : (j == 2) ? y2 : y3;

            float e  = __expf(fmaf(x, c2, b2));
            float th = 1.0f - __fdividef(2.0f, e + 1.0f);      // tanh(x*c+bs)
            float idx = fmaf(th, 8.5f, 1.0f);                  // 1 + tanh/2*17
            float fb  = floorf(idx);
            float pos = idx - fb;
            int bgn = (int)fb;
            int end = bgn + 1;                                 // end < 17 always here
            if (bgn < 0) bgn += NUM_POINTS;                    // torch negative wrap
            if (end < 0) end += NUM_POINTS;

            float vb = s_vel[bgn], ve = s_vel[end];
            float ab = s_ang[bgn], ae = s_ang[end];
            float velo = fmaf(pos, ve - vb, vb);
            float ang  = fmaf(pos, ae - ab, ab);

            float sn, cs;
            __sincosf(ang, &sn, &cs);
            float stepv = fmaf(x, velo * sn, velo * cs);
            x = fmaf(stepv, 0.33333333333333333f, x);

            if (j == 0) y0 = x; else if (j == 1) y1 = x; else if (j == 2) y2 = x; else y3 = x;
        }
    }

    // g -> (row b, channel-group c4): 128 float4-groups of input per row.
    const int brow = g >> 7;
    const int c4   = g & 127;

    const float4 a0 = __ldg(&att[2 * c4]);
    const float4 a1 = __ldg(&att[2 * c4 + 1]);

    float4 o0, o1;
    o0.x = a0.x * y0;  o0.y = a0.y * y0;
    o0.z = a0.z * y1;  o0.w = a0.w * y1;
    o1.x = a1.x * y2;  o1.y = a1.y * y2;
    o1.z = a1.z * y3;  o1.w = a1.w * y3;

    const int ob = brow * 256 + 2 * c4;          // 256 float4 per output row
    out[ob]     = o0;
    out[ob + 1] = o1;
}

extern "C" void kernel_launch(void* const* d_in, const int* in_sizes, int n_in,
                              void* d_out, int out_size)
{
    const float4* data    = (const float4*)d_in[0];   // [32768, 512] f32
    const float*  angles  = (const float*) d_in[1];   // [17]
    const float*  velocity= (const float*) d_in[2];   // [17]
    const float4* att     = (const float4*)d_in[3];   // [1024] f32
    const float*  coeff   = (const float*) d_in[4];   // [1]
    const float*  bias    = (const float*) d_in[5];   // [1]
    float4* out = (float4*)d_out;

    const int total_groups = (32768 * 512) / 4;       // 4,194,304 threads
    const int threads = 256;
    const int blocks = total_groups / threads;        // 16,384
    macunit_kernel<<<blocks, threads>>>(data, angles, velocity, att, coeff, bias, out);
}

// round 2
// speedup vs baseline: 1.0654x; 1.0654x over previous
#include <cuda_runtime.h>

// MacUnit: out[b, 2*ic+k] = attention[2*ic+k] * f3(data[b, ic])
// f3 = 3 iterations of x += step(x)/3,
// step(x) = velo*cos(ang) + x*velo*sin(ang) with (velo, ang) linearly
// interpolated from 17-entry tables at index = 1 + tanh(c*x+b)/2*17.
//
// Index analysis: tanh in (-1,1) => index in (-7.5, 9.5) => bgn in [-8, 9],
// end = bgn+1 <= 10 < 17 (the "lt" branch is always taken). So there are
// exactly 18 possible segments; we precompute per-segment
// (vb/3, dv/3, ab, da) with torch negative-index wrapping folded in, and the
// inner loop does ONE LDS.128 + 2 lerp FMAs + sincos.

#define NUM_POINTS 17

__global__ __launch_bounds__(256, 8)
void macunit_kernel(const float4* __restrict__ data,
                    const float* __restrict__ angles,
                    const float* __restrict__ velocity,
                    const float4* __restrict__ att,     // 1024 floats = 256 float4
                    const float* __restrict__ coeff,
                    const float* __restrict__ bias,
                    float4* __restrict__ out)           // [B, 256] float4
{
    __shared__ float4 s_seg[18];   // (vb/3, dv/3, ab, da) for bgn = j-8

    const int t = threadIdx.x;
    if (t < 18) {
        int bgn = t - 8;
        int end = bgn + 1;
        int bw = bgn < 0 ? bgn + NUM_POINTS : bgn;   // torch negative wrap
        int ew = end < 0 ? end + NUM_POINTS : end;
        float vb = velocity[bw] * (1.0f / 3.0f);
        float ve = velocity[ew] * (1.0f / 3.0f);
        float ab = angles[bw];
        float ae = angles[ew];
        s_seg[t] = make_float4(vb, ve - vb, ab, ae - ab);
    }
    __syncthreads();

    // e^{2z} = 2^{(2*log2e*c)*x + (2*log2e)*b}
    const float c2l = __ldg(coeff) * 2.8853900817779268f;  // 2*log2(e)*c
    const float b2l = __ldg(bias)  * 2.8853900817779268f;  // 2*log2(e)*b

    const int g = blockIdx.x * 256 + t;          // 0 .. B*IN_CH/4 - 1
    const float4 d = data[g];

    float y0 = d.x, y1 = d.y, y2 = d.z, y3 = d.w;

    #pragma unroll
    for (int s = 0; s < 3; s++) {
        #pragma unroll
        for (int j = 0; j < 4; j++) {
            float x = (j == 0) ? y0 : (j == 1) ? y1 : (j == 2) ? y2 : y3;

            // u = index + 8 = 17.5 - 17/(e^{2z}+1), in (0.5, 17.5)
            float e;
            asm("ex2.approx.f32 %0, %1;" : "=f"(e) : "f"(fmaf(x, c2l, b2l)));
            float r;
            asm("rcp.approx.f32 %0, %1;" : "=f"(r) : "f"(e + 1.0f));
            float u   = fmaf(r, -17.0f, 17.5f);
            float fb  = floorf(u);
            float pos = u - fb;
            int   seg = (int)fb;                    // 0..17

            float4 sg = s_seg[seg];                 // one LDS.128
            float velo3 = fmaf(pos, sg.y, sg.x);    // velo/3
            float ang   = fmaf(pos, sg.w, sg.z);

            float sn, cs;
            __sincosf(ang, &sn, &cs);
            float a = velo3 * sn;
            float c = velo3 * cs;
            x = fmaf(x, 1.0f + a, c);               // x + (velo*cos + x*velo*sin)/3

            if (j == 0) y0 = x; else if (j == 1) y1 = x; else if (j == 2) y2 = x; else y3 = x;
        }
    }

    // g -> (row b, channel-group c4): 128 float4-groups of input per row.
    const int brow = g >> 7;
    const int c4   = g & 127;

    const float4 a0 = __ldg(&att[2 * c4]);
    const float4 a1 = __ldg(&att[2 * c4 + 1]);

    float4 o0, o1;
    o0.x = a0.x * y0;  o0.y = a0.y * y0;
    o0.z = a0.z * y1;  o0.w = a0.w * y1;
    o1.x = a1.x * y2;  o1.y = a1.y * y2;
    o1.z = a1.z * y3;  o1.w = a1.w * y3;

    const int ob = brow * 256 + 2 * c4;          // 256 float4 per output row
    out[ob]     = o0;
    out[ob + 1] = o1;
}

extern "C" void kernel_launch(void* const* d_in, const int* in_sizes, int n_in,
                              void* d_out, int out_size)
{
    const float4* data    = (const float4*)d_in[0];   // [32768, 512] f32
    const float*  angles  = (const float*) d_in[1];   // [17]
    const float*  velocity= (const float*) d_in[2];   // [17]
    const float4* att     = (const float4*)d_in[3];   // [1024] f32
    const float*  coeff   = (const float*) d_in[4];   // [1]
    const float*  bias    = (const float*) d_in[5];   // [1]
    float4* out = (float4*)d_out;

    const int total_groups = (32768 * 512) / 4;       // 4,194,304 threads
    const int threads = 256;
    const int blocks = total_groups / threads;        // 16,384
    macunit_kernel<<<blocks, threads>>>(data, angles, velocity, att, coeff, bias, out);
}

// round 3
// speedup vs baseline: 1.1436x; 1.0734x over previous
#include <cuda_runtime.h>

// MacUnit: out[b, 2*ic+k] = attention[2*ic+k] * f3(data[b, ic])
// f3 = 3 iterations of x += step(x)/3,
// step(x) = velo*cos(ang) + x*velo*sin(ang), (velo, ang) lerped from 17-entry
// tables at index = 1 + tanh(c*x+b)/2*17.
//
// index in (-7.5, 9.5) => bgn in [-8, 9], end=bgn+1 < 17 always. 18 segments.
// Segment table (vb/3, dv/3, ab, da) lives in REGISTERS of lanes 0..17 of every
// warp; lookup is 4x SHFL.IDX -- zero shared-memory traffic, zero bank
// conflicts (R2 showed LDS.128 lookups saturating L1 at 81%).

#define NUM_POINTS 17

__global__ __launch_bounds__(256)
void macunit_kernel(const float4* __restrict__ data,
                    const float* __restrict__ angles,
                    const float* __restrict__ velocity,
                    const float4* __restrict__ att,     // 1024 floats = 256 float4
                    const float* __restrict__ coeff,
                    const float* __restrict__ bias,
                    float4* __restrict__ out)           // [B, 256] float4
{
    const int t    = threadIdx.x;
    const int lane = t & 31;

    // Per-warp register-resident segment table (lanes 0..17 hold real data).
    float r_vb3 = 0.f, r_dv3 = 0.f, r_ab = 0.f, r_da = 0.f;
    if (lane < 18) {
        int bgn = lane - 8;
        int end = bgn + 1;
        int bw = bgn < 0 ? bgn + NUM_POINTS : bgn;    // torch negative wrap
        int ew = end < 0 ? end + NUM_POINTS : end;
        float vb = __ldg(&velocity[bw]) * (1.0f / 3.0f);
        float ve = __ldg(&velocity[ew]) * (1.0f / 3.0f);
        r_vb3 = vb;
        r_dv3 = ve - vb;
        r_ab  = __ldg(&angles[bw]);
        r_da  = __ldg(&angles[ew]) - r_ab;
    }

    // e^{2z} = 2^{(2*log2e*c)*x + (2*log2e)*b}
    const float c2l = __ldg(coeff) * 2.8853900817779268f;
    const float b2l = __ldg(bias)  * 2.8853900817779268f;

    const int g = blockIdx.x * 256 + t;               // 0 .. B*IN_CH/4 - 1
    const float4 d = data[g];

    float y[4] = {d.x, d.y, d.z, d.w};

    #pragma unroll
    for (int s = 0; s < 3; s++) {
        float pos[4];
        int   seg[4];

        // Phase 1: tanh-index for all 4 chains (batches EX2/RCP on the MUFU pipe)
        #pragma unroll
        for (int j = 0; j < 4; j++) {
            float e;
            asm("ex2.approx.f32 %0, %1;" : "=f"(e) : "f"(fmaf(y[j], c2l, b2l)));
            float r;
            asm("rcp.approx.f32 %0, %1;" : "=f"(r) : "f"(e + 1.0f));
            float u = fmaf(r, -17.0f, 17.5f);         // index + 8, in (0.5, 17.5)
            int   si = (int)u;                        // trunc == floor (u > 0)
            seg[j] = si;
            pos[j] = u - (float)si;
        }

        // Phase 2: register-table lookup via shuffle + trig update
        #pragma unroll
        for (int j = 0; j < 4; j++) {
            float vb = __shfl_sync(0xffffffffu, r_vb3, seg[j]);
            float dv = __shfl_sync(0xffffffffu, r_dv3, seg[j]);
            float ab = __shfl_sync(0xffffffffu, r_ab,  seg[j]);
            float da = __shfl_sync(0xffffffffu, r_da,  seg[j]);
            float velo3 = fmaf(pos[j], dv, vb);       // velo/3
            float ang   = fmaf(pos[j], da, ab);
            float sn, cs;
            __sincosf(ang, &sn, &cs);
            y[j] = fmaf(y[j], fmaf(velo3, sn, 1.0f), velo3 * cs);
        }
    }

    // g -> (row b, channel-group c4): 128 float4-groups of input per row.
    const int brow = g >> 7;
    const int c4   = g & 127;

    const float4 a0 = __ldg(&att[2 * c4]);
    const float4 a1 = __ldg(&att[2 * c4 + 1]);

    float4 o0, o1;
    o0.x = a0.x * y[0];  o0.y = a0.y * y[0];
    o0.z = a0.z * y[1];  o0.w = a0.w * y[1];
    o1.x = a1.x * y[2];  o1.y = a1.y * y[2];
    o1.z = a1.z * y[3];  o1.w = a1.w * y[3];

    const int ob = brow * 256 + 2 * c4;               // 256 float4 per output row
    out[ob]     = o0;
    out[ob + 1] = o1;
}

extern "C" void kernel_launch(void* const* d_in, const int* in_sizes, int n_in,
                              void* d_out, int out_size)
{
    const float4* data     = (const float4*)d_in[0];  // [32768, 512] f32
    const float*  angles   = (const float*) d_in[1];  // [17]
    const float*  velocity = (const float*) d_in[2];  // [17]
    const float4* att      = (const float4*)d_in[3];  // [1024] f32
    const float*  coeff    = (const float*) d_in[4];  // [1]
    const float*  bias     = (const float*) d_in[5];  // [1]
    float4* out = (float4*)d_out;

    const int total_groups = (32768 * 512) / 4;       // 4,194,304 threads
    const int threads = 256;
    const int blocks = total_groups / threads;        // 16,384
    macunit_kernel<<<blocks, threads>>>(data, angles, velocity, att, coeff, bias, out);
}